// round 15
// baseline (speedup 1.0000x reference)
#include <cuda_runtime.h>
#include <cuda_bf16.h>
#include <cstdint>

// ---------------------------------------------------------------------------
// Problem shape (fixed by the dataset)
// ---------------------------------------------------------------------------
#define DIMK 2048
#define NB   4096
#define NM   12893

// GEMM tiling — 128x128 CTA tile, 2-stage pipeline (64KB smem) -> 3 CTAs/SM
#define BM 128            // CTA rows (x)
#define BN 128            // CTA cols (prototypes)
#define BK 64             // k per pipeline stage (64 bf16 = 128 B rows)
#define NKT (DIMK / BK)   // 32
#define STAGES 2
#define STG_A (BM * 128)          // 16384 B
#define STG_B (BN * 128)          // 16384 B
#define STG_BYTES (STG_A + STG_B) // 32768 B
#define SMEM_DYN (STAGES * STG_BYTES)  // 65536 B -> 3 CTAs = 192KB/SM

#define NTHREADS 256      // 8 warps (2m x 4n), warp tile 64x32

// Scratch: normalized bf16 copies (bss, fixed addresses)
__device__ __align__(1024) __nv_bfloat16 g_xn[(size_t)NB * DIMK];
__device__ __align__(1024) __nv_bfloat16 g_pn[(size_t)NM * DIMK];

// ---------------------------------------------------------------------------
// Kernel 1: per-row L2 normalize fp32 -> bf16 (one block per row)
// ---------------------------------------------------------------------------
__global__ __launch_bounds__(256) void normalize_rows(
    const float* __restrict__ in, __nv_bfloat16* __restrict__ out)
{
    const int row = blockIdx.x;
    const int t   = threadIdx.x;
    const float4* rin = reinterpret_cast<const float4*>(in + (size_t)row * DIMK);

    float4 v0 = rin[t];
    float4 v1 = rin[t + 256];

    float s = v0.x*v0.x + v0.y*v0.y + v0.z*v0.z + v0.w*v0.w
            + v1.x*v1.x + v1.y*v1.y + v1.z*v1.z + v1.w*v1.w;

    #pragma unroll
    for (int o = 16; o > 0; o >>= 1)
        s += __shfl_xor_sync(0xffffffffu, s, o);

    __shared__ float red[8];
    __shared__ float s_inv;
    if ((t & 31) == 0) red[t >> 5] = s;
    __syncthreads();
    if (t == 0) {
        float tot = 0.f;
        #pragma unroll
        for (int i = 0; i < 8; ++i) tot += red[i];
        s_inv = 1.0f / fmaxf(sqrtf(tot), 1e-12f);
    }
    __syncthreads();
    const float inv = s_inv;

    uint2* ro = reinterpret_cast<uint2*>(out + (size_t)row * DIMK);

    __nv_bfloat162 h0 = __floats2bfloat162_rn(v0.x * inv, v0.y * inv);
    __nv_bfloat162 h1 = __floats2bfloat162_rn(v0.z * inv, v0.w * inv);
    uint2 p0;
    p0.x = *reinterpret_cast<uint32_t*>(&h0);
    p0.y = *reinterpret_cast<uint32_t*>(&h1);
    ro[t] = p0;

    __nv_bfloat162 h2 = __floats2bfloat162_rn(v1.x * inv, v1.y * inv);
    __nv_bfloat162 h3 = __floats2bfloat162_rn(v1.z * inv, v1.w * inv);
    uint2 p1;
    p1.x = *reinterpret_cast<uint32_t*>(&h2);
    p1.y = *reinterpret_cast<uint32_t*>(&h3);
    ro[t + 256] = p1;
}

// ---------------------------------------------------------------------------
// primitives (sm_80-era: valid on base sm_103 target)
// ---------------------------------------------------------------------------
__device__ __forceinline__ void cpa16(uint32_t smem, const void* g) {
    asm volatile("cp.async.cg.shared.global [%0], [%1], 16;" :: "r"(smem), "l"(g));
}
__device__ __forceinline__ void cpa16z(uint32_t smem, const void* g, uint32_t n) {
    asm volatile("cp.async.cg.shared.global [%0], [%1], 16, %2;"
                 :: "r"(smem), "l"(g), "r"(n));
}
__device__ __forceinline__ void cp_commit() {
    asm volatile("cp.async.commit_group;");
}
__device__ __forceinline__ void cp_wait0() {
    asm volatile("cp.async.wait_group 0;");
}

__device__ __forceinline__ void ldmx4(uint32_t& r0, uint32_t& r1,
                                      uint32_t& r2, uint32_t& r3, uint32_t a) {
    asm volatile("ldmatrix.sync.aligned.m8n8.x4.shared.b16 {%0,%1,%2,%3}, [%4];"
                 : "=r"(r0), "=r"(r1), "=r"(r2), "=r"(r3) : "r"(a));
}

__device__ __forceinline__ void mma16816(float* c, const uint32_t* a, const uint32_t* b)
{
    asm volatile(
        "mma.sync.aligned.m16n8k16.row.col.f32.bf16.bf16.f32 "
        "{%0,%1,%2,%3}, {%4,%5,%6,%7}, {%8,%9}, {%0,%1,%2,%3};"
        : "+f"(c[0]), "+f"(c[1]), "+f"(c[2]), "+f"(c[3])
        : "r"(a[0]), "r"(a[1]), "r"(a[2]), "r"(a[3]),
          "r"(b[0]), "r"(b[1]));
}

// ---------------------------------------------------------------------------
// Kernel 2: GEMM  C[b,m] = -|s| * sqrt(max(2 - 2*dot, 0))
//   CTA 128x128xK, 8 warps (2m x 4n), warp tile 64x32, 3 CTAs/SM
//   2-stage cp.async pipeline, ldmatrix.x4, SW128 xor swizzle
//   Inner loop B-first, A fragment per-mt -> minimal live registers (85 cap)
//   NOTE: M = 12893 is ODD -> scalar epilogue stores only.
// ---------------------------------------------------------------------------
__global__ __launch_bounds__(NTHREADS, 3) void isomax_gemm(
    const float* __restrict__ scale, float* __restrict__ out, int M)
{
    extern __shared__ char smem[];
    const uint32_t sbase = (uint32_t)__cvta_generic_to_shared(smem);

    const int t    = threadIdx.x;
    const int lane = t & 31;
    const int w    = t >> 5;
    const int wm   = w >> 2;          // 0..1  -> 64-row slab (m)
    const int wn   = w & 3;           // 0..3  -> 32-col slab (n)
    const int g    = lane >> 2;       // 0..7
    const int tq   = lane & 3;        // 0..3

    const int tileM0 = blockIdx.y * BM;
    const int tileN0 = blockIdx.x * BN;

    float acc[4][4][4];               // [mt][nt][frag] = 64 regs
    #pragma unroll
    for (int mt = 0; mt < 4; ++mt)
        #pragma unroll
        for (int nt = 0; nt < 4; ++nt)
            #pragma unroll
            for (int r = 0; r < 4; ++r) acc[mt][nt][r] = 0.f;

    // ---- cp.async stage issue: 2048 16B-chunks over 256 threads (8 each) ----
    auto issue_stage = [&](int kt) {
        const int st = kt % STAGES;
        const int k0 = kt * BK;
        const uint32_t aB = sbase + st * STG_BYTES;
        const uint32_t bB = aB + STG_A;
        #pragma unroll
        for (int i = 0; i < 8; ++i) {
            const int c = t + i * NTHREADS;
            if (i < 4) {               // A: 1024 chunks
                const int row = c >> 3, ch = c & 7;
                const uint32_t dst = aB + (uint32_t)(row * 128 + ((ch ^ (row & 7)) * 16));
                cpa16(dst, g_xn + (size_t)(tileM0 + row) * DIMK + k0 + ch * 8);
            } else {                   // B: 1024 chunks
                const int cb = c - 1024;
                const int row = cb >> 3, ch = cb & 7;
                const uint32_t dst = bB + (uint32_t)(row * 128 + ((ch ^ (row & 7)) * 16));
                const int grow = tileN0 + row;
                cpa16z(dst, g_pn + (size_t)grow * DIMK + k0 + ch * 8,
                       (grow < NM) ? 16u : 0u);
            }
        }
    };

    issue_stage(0); cp_commit();

    // ldmatrix per-lane invariants
    const int aRow = wm * 64 + (lane & 15);          // + mt*16
    const int aCs  = lane >> 4;                      // chunk select 0/1
    const int bRow = wn * 32 + ((lane >> 4) << 3) + (lane & 7);  // + bt*16
    const int bCs  = (lane >> 3) & 1;
    const int loXor = lane & 7;

    #pragma unroll 1
    for (int kt = 0; kt < NKT; ++kt) {
        cp_wait0();
        __syncthreads();
        if (kt + 1 < NKT) { issue_stage(kt + 1); cp_commit(); }

        const int st = kt % STAGES;
        const uint32_t aB = sbase + st * STG_BYTES;
        const uint32_t bB = aB + STG_A;

        #pragma unroll
        for (int ks = 0; ks < 4; ++ks) {
            // B fragments first (stay live across the mt loop: 8 regs)
            uint32_t bf[2][4];
            #pragma unroll
            for (int bt = 0; bt < 2; ++bt) {
                const int row = bRow + bt * 16;
                const uint32_t bd = bB + (uint32_t)(row * 128 +
                                     (((ks * 2 + bCs) ^ loXor) * 16));
                ldmx4(bf[bt][0], bf[bt][1], bf[bt][2], bf[bt][3], bd);
            }
            // A fragment per mt (4 regs live at a time)
            #pragma unroll
            for (int mt = 0; mt < 4; ++mt) {
                uint32_t a0, a1, a2, a3;
                const int row = aRow + mt * 16;
                const uint32_t ad = aB + (uint32_t)(row * 128 +
                                     (((ks * 2 + aCs) ^ loXor) * 16));
                ldmx4(a0, a1, a2, a3, ad);
                uint32_t af[4] = {a0, a1, a2, a3};
                mma16816(acc[mt][0], af, &bf[0][0]);
                mma16816(acc[mt][1], af, &bf[0][2]);
                mma16816(acc[mt][2], af, &bf[1][0]);
                mma16816(acc[mt][3], af, &bf[1][2]);
            }
        }
    }

    // ---- epilogue: -|s| * sqrt(max(2 - 2*dot, 0)) — scalar stores only ----
    const float sgn = fabsf(scale[0]);
    #pragma unroll
    for (int mt = 0; mt < 4; ++mt) {
        const int r0 = tileM0 + wm * 64 + mt * 16 + g;
        float* o0 = out + (size_t)r0 * M;
        float* o1 = out + (size_t)(r0 + 8) * M;
        #pragma unroll
        for (int nt = 0; nt < 4; ++nt) {
            const int col = tileN0 + wn * 32 + nt * 8 + tq * 2;
            const float* c = acc[mt][nt];
            if (col < M) {
                o0[col] = -sgn * sqrtf(fmaxf(2.0f - 2.0f * c[0], 0.0f));
                o1[col] = -sgn * sqrtf(fmaxf(2.0f - 2.0f * c[2], 0.0f));
                if (col + 1 < M) {
                    o0[col + 1] = -sgn * sqrtf(fmaxf(2.0f - 2.0f * c[1], 0.0f));
                    o1[col + 1] = -sgn * sqrtf(fmaxf(2.0f - 2.0f * c[3], 0.0f));
                }
            }
        }
    }
}

// ---------------------------------------------------------------------------
extern "C" void kernel_launch(void* const* d_in, const int* in_sizes, int n_in,
                              void* d_out, int out_size)
{
    const float* x     = (const float*)d_in[0];
    const float* prot  = (const float*)d_in[1];
    const float* scale = (const float*)d_in[2];
    float* out = (float*)d_out;

    const int B = in_sizes[0] / DIMK;   // 4096
    const int M = in_sizes[1] / DIMK;   // 12893

    __nv_bfloat16 *xn_p, *pn_p;
    cudaGetSymbolAddress((void**)&xn_p, g_xn);
    cudaGetSymbolAddress((void**)&pn_p, g_pn);

    normalize_rows<<<B, 256>>>(x, xn_p);
    normalize_rows<<<M, 256>>>(prot, pn_p);

    cudaFuncSetAttribute(isomax_gemm, cudaFuncAttributeMaxDynamicSharedMemorySize,
                         SMEM_DYN);

    dim3 grid((M + BN - 1) / BN, B / BM);   // 101 x 32 = 3232 CTAs
    isomax_gemm<<<grid, NTHREADS, SMEM_DYN>>>(scale, out, M);
}

// round 16
// speedup vs baseline: 1.9016x; 1.9016x over previous
#include <cuda_runtime.h>
#include <cuda_bf16.h>
#include <cstdint>

// ---------------------------------------------------------------------------
// Problem shape (fixed by the dataset)
// ---------------------------------------------------------------------------
#define DIMK 2048
#define NB   4096
#define NM   12893

// GEMM tiling — 128x128 CTA tile, 96KB smem -> 2 CTAs/SM (R14 proven config)
#define BM 128            // CTA rows (x)
#define BN 128            // CTA cols (prototypes)
#define BK 64             // k per pipeline stage (64 bf16 = 128 B rows)
#define NKT (DIMK / BK)   // 32
#define STAGES 3
#define STG_A (BM * 128)          // 16384 B
#define STG_B (BN * 128)          // 16384 B
#define STG_BYTES (STG_A + STG_B) // 32768 B
#define SMEM_DYN (STAGES * STG_BYTES)  // 98304 B -> two CTAs = 192KB/SM

#define NTHREADS 256      // 8 warps (2m x 4n), warp tile 64x32

// Scratch: normalized bf16 copies (bss, fixed addresses)
__device__ __align__(1024) __nv_bfloat16 g_xn[(size_t)NB * DIMK];
__device__ __align__(1024) __nv_bfloat16 g_pn[(size_t)NM * DIMK];

// ---------------------------------------------------------------------------
// Kernel 1: per-row L2 normalize fp32 -> bf16, ONE WARP PER ROW
//   lane holds 16 float4 (64 floats) -> warp-shfl reduce, no smem, no barriers
//   256 threads = 8 rows per block
// ---------------------------------------------------------------------------
__global__ __launch_bounds__(256) void normalize_rows_w(
    const float* __restrict__ in, __nv_bfloat16* __restrict__ out, int nrows)
{
    const int lane = threadIdx.x & 31;
    const int row  = blockIdx.x * 8 + (threadIdx.x >> 5);
    if (row >= nrows) return;

    const float4* rin = reinterpret_cast<const float4*>(in + (size_t)row * DIMK);

    float4 v[16];
    #pragma unroll
    for (int j = 0; j < 16; ++j)
        v[j] = rin[lane + 32 * j];

    float s = 0.f;
    #pragma unroll
    for (int j = 0; j < 16; ++j)
        s += v[j].x * v[j].x + v[j].y * v[j].y + v[j].z * v[j].z + v[j].w * v[j].w;

    #pragma unroll
    for (int o = 16; o > 0; o >>= 1)
        s += __shfl_xor_sync(0xffffffffu, s, o);

    const float inv = 1.0f / fmaxf(sqrtf(s), 1e-12f);

    uint2* ro = reinterpret_cast<uint2*>(out + (size_t)row * DIMK);
    #pragma unroll
    for (int j = 0; j < 16; ++j) {
        __nv_bfloat162 h0 = __floats2bfloat162_rn(v[j].x * inv, v[j].y * inv);
        __nv_bfloat162 h1 = __floats2bfloat162_rn(v[j].z * inv, v[j].w * inv);
        uint2 p;
        p.x = *reinterpret_cast<uint32_t*>(&h0);
        p.y = *reinterpret_cast<uint32_t*>(&h1);
        ro[lane + 32 * j] = p;
    }
}

// ---------------------------------------------------------------------------
// primitives (sm_80-era: valid on base sm_103 target)
// ---------------------------------------------------------------------------
__device__ __forceinline__ void cpa16(uint32_t smem, const void* g) {
    asm volatile("cp.async.cg.shared.global [%0], [%1], 16;" :: "r"(smem), "l"(g));
}
__device__ __forceinline__ void cpa16z(uint32_t smem, const void* g, uint32_t n) {
    asm volatile("cp.async.cg.shared.global [%0], [%1], 16, %2;"
                 :: "r"(smem), "l"(g), "r"(n));
}
__device__ __forceinline__ void cp_commit() {
    asm volatile("cp.async.commit_group;");
}
__device__ __forceinline__ void cp_wait1() {
    asm volatile("cp.async.wait_group 1;");
}

__device__ __forceinline__ void ldmx4(uint32_t& r0, uint32_t& r1,
                                      uint32_t& r2, uint32_t& r3, uint32_t a) {
    asm volatile("ldmatrix.sync.aligned.m8n8.x4.shared.b16 {%0,%1,%2,%3}, [%4];"
                 : "=r"(r0), "=r"(r1), "=r"(r2), "=r"(r3) : "r"(a));
}

__device__ __forceinline__ void mma16816(float* c, const uint32_t* a, const uint32_t* b)
{
    asm volatile(
        "mma.sync.aligned.m16n8k16.row.col.f32.bf16.bf16.f32 "
        "{%0,%1,%2,%3}, {%4,%5,%6,%7}, {%8,%9}, {%0,%1,%2,%3};"
        : "+f"(c[0]), "+f"(c[1]), "+f"(c[2]), "+f"(c[3])
        : "r"(a[0]), "r"(a[1]), "r"(a[2]), "r"(a[3]),
          "r"(b[0]), "r"(b[1]));
}

// ---------------------------------------------------------------------------
// Kernel 2: GEMM  C[b,m] = -|s| * sqrt(max(2 - 2*dot, 0))
//   CTA 128x128xK, 8 warps (2m x 4n), warp tile 64x32, 2 CTAs/SM
//   3-stage cp.async pipeline, ldmatrix.x4, SW128 xor swizzle  (R14 verbatim)
//   NOTE: M = 12893 is ODD -> scalar epilogue stores only.
// ---------------------------------------------------------------------------
__global__ __launch_bounds__(NTHREADS, 2) void isomax_gemm(
    const float* __restrict__ scale, float* __restrict__ out, int M)
{
    extern __shared__ char smem[];
    const uint32_t sbase = (uint32_t)__cvta_generic_to_shared(smem);

    const int t    = threadIdx.x;
    const int lane = t & 31;
    const int w    = t >> 5;
    const int wm   = w >> 2;          // 0..1  -> 64-row slab (m)
    const int wn   = w & 3;           // 0..3  -> 32-col slab (n)
    const int g    = lane >> 2;       // 0..7
    const int tq   = lane & 3;        // 0..3

    const int tileM0 = blockIdx.y * BM;
    const int tileN0 = blockIdx.x * BN;

    float acc[4][4][4];               // [mt][nt][frag] = 64 regs
    #pragma unroll
    for (int mt = 0; mt < 4; ++mt)
        #pragma unroll
        for (int nt = 0; nt < 4; ++nt)
            #pragma unroll
            for (int r = 0; r < 4; ++r) acc[mt][nt][r] = 0.f;

    // ---- cp.async stage issue: 2048 16B-chunks over 256 threads (8 each) ----
    auto issue_stage = [&](int kt) {
        const int st = kt % STAGES;
        const int k0 = kt * BK;
        const uint32_t aB = sbase + st * STG_BYTES;
        const uint32_t bB = aB + STG_A;
        #pragma unroll
        for (int i = 0; i < 8; ++i) {
            const int c = t + i * NTHREADS;
            if (i < 4) {               // A: 1024 chunks
                const int row = c >> 3, ch = c & 7;
                const uint32_t dst = aB + (uint32_t)(row * 128 + ((ch ^ (row & 7)) * 16));
                cpa16(dst, g_xn + (size_t)(tileM0 + row) * DIMK + k0 + ch * 8);
            } else {                   // B: 1024 chunks
                const int cb = c - 1024;
                const int row = cb >> 3, ch = cb & 7;
                const uint32_t dst = bB + (uint32_t)(row * 128 + ((ch ^ (row & 7)) * 16));
                const int grow = tileN0 + row;
                cpa16z(dst, g_pn + (size_t)grow * DIMK + k0 + ch * 8,
                       (grow < NM) ? 16u : 0u);
            }
        }
    };

    issue_stage(0); cp_commit();
    issue_stage(1); cp_commit();

    // ldmatrix per-lane invariants
    const int aRow = wm * 64 + (lane & 15);          // + mt*16
    const int aCs  = lane >> 4;                      // chunk select 0/1
    const int bRow = wn * 32 + ((lane >> 4) << 3) + (lane & 7);  // + bt*16
    const int bCs  = (lane >> 3) & 1;
    const int loXor = lane & 7;

    #pragma unroll 1
    for (int kt = 0; kt < NKT; ++kt) {
        cp_wait1();
        __syncthreads();
        if (kt + 2 < NKT) issue_stage(kt + 2);
        cp_commit();

        const int st = kt % STAGES;
        const uint32_t aB = sbase + st * STG_BYTES;
        const uint32_t bB = aB + STG_A;

        #pragma unroll
        for (int ks = 0; ks < 4; ++ks) {
            uint32_t af[4][4];
            uint32_t bf[2][4];
            #pragma unroll
            for (int mt = 0; mt < 4; ++mt) {
                const int row = aRow + mt * 16;
                const uint32_t ad = aB + (uint32_t)(row * 128 +
                                     (((ks * 2 + aCs) ^ loXor) * 16));
                ldmx4(af[mt][0], af[mt][1], af[mt][2], af[mt][3], ad);
            }
            #pragma unroll
            for (int bt = 0; bt < 2; ++bt) {
                const int row = bRow + bt * 16;
                const uint32_t bd = bB + (uint32_t)(row * 128 +
                                     (((ks * 2 + bCs) ^ loXor) * 16));
                ldmx4(bf[bt][0], bf[bt][1], bf[bt][2], bf[bt][3], bd);
            }
            #pragma unroll
            for (int mt = 0; mt < 4; ++mt)
                #pragma unroll
                for (int bt = 0; bt < 2; ++bt) {
                    mma16816(acc[mt][bt * 2 + 0], af[mt], &bf[bt][0]);  // n lo 8
                    mma16816(acc[mt][bt * 2 + 1], af[mt], &bf[bt][2]);  // n hi 8
                }
        }
    }

    // ---- epilogue: -|s| * sqrt(max(2 - 2*dot, 0)) — scalar stores only ----
    const float sgn = fabsf(scale[0]);
    #pragma unroll
    for (int mt = 0; mt < 4; ++mt) {
        const int r0 = tileM0 + wm * 64 + mt * 16 + g;
        float* o0 = out + (size_t)r0 * M;
        float* o1 = out + (size_t)(r0 + 8) * M;
        #pragma unroll
        for (int nt = 0; nt < 4; ++nt) {
            const int col = tileN0 + wn * 32 + nt * 8 + tq * 2;
            const float* c = acc[mt][nt];
            if (col < M) {
                o0[col] = -sgn * sqrtf(fmaxf(2.0f - 2.0f * c[0], 0.0f));
                o1[col] = -sgn * sqrtf(fmaxf(2.0f - 2.0f * c[2], 0.0f));
                if (col + 1 < M) {
                    o0[col + 1] = -sgn * sqrtf(fmaxf(2.0f - 2.0f * c[1], 0.0f));
                    o1[col + 1] = -sgn * sqrtf(fmaxf(2.0f - 2.0f * c[3], 0.0f));
                }
            }
        }
    }
}

// ---------------------------------------------------------------------------
extern "C" void kernel_launch(void* const* d_in, const int* in_sizes, int n_in,
                              void* d_out, int out_size)
{
    const float* x     = (const float*)d_in[0];
    const float* prot  = (const float*)d_in[1];
    const float* scale = (const float*)d_in[2];
    float* out = (float*)d_out;

    const int B = in_sizes[0] / DIMK;   // 4096
    const int M = in_sizes[1] / DIMK;   // 12893

    __nv_bfloat16 *xn_p, *pn_p;
    cudaGetSymbolAddress((void**)&xn_p, g_xn);
    cudaGetSymbolAddress((void**)&pn_p, g_pn);

    normalize_rows_w<<<(B + 7) / 8, 256>>>(x, xn_p, B);
    normalize_rows_w<<<(M + 7) / 8, 256>>>(prot, pn_p, M);

    cudaFuncSetAttribute(isomax_gemm, cudaFuncAttributeMaxDynamicSharedMemorySize,
                         SMEM_DYN);

    dim3 grid((M + BN - 1) / BN, B / BM);   // 101 x 32 = 3232 CTAs
    isomax_gemm<<<grid, NTHREADS, SMEM_DYN>>>(scale, out, M);
}